// round 4
// baseline (speedup 1.0000x reference)
#include <cuda_runtime.h>
#include <cuda_bf16.h>

#define N_ROWS 8192
#define F_DIM  512
#define K_KEEP 4096
#define NBLK   148
#define NT     512

// Scratch (device globals — no allocation allowed)
__device__ __align__(16) float g_y[N_ROWS];
__device__ float g_inv_norm;
__device__ __align__(16) int   g_idx[K_KEEP];
__device__ unsigned g_bar_count = 0;   // self-resets each barrier
__device__ unsigned g_bar_epoch = 0;   // monotonically increases across launches

// ---------------------------------------------------------------------------
// Grid barrier (all NBLK blocks resident). e0 = epoch at kernel entry.
// Blocks until g_bar_epoch has advanced n times past e0.
// ---------------------------------------------------------------------------
__device__ __forceinline__ void grid_barrier(int n, unsigned e0)
{
    __syncthreads();
    if (threadIdx.x == 0) {
        __threadfence();
        unsigned prev = atomicAdd(&g_bar_count, 1);
        if (prev == NBLK - 1) {
            g_bar_count = 0;
            __threadfence();
            atomicAdd(&g_bar_epoch, 1);
        } else {
            int backoff = 32;
            while (*(volatile unsigned*)&g_bar_epoch - e0 < (unsigned)n) {
                __nanosleep(backoff);
                if (backoff < 256) backoff <<= 1;
            }
        }
        __threadfence();
    }
    __syncthreads();
}

// ---------------------------------------------------------------------------
// Block scans for 512 threads (16 warps)
// ---------------------------------------------------------------------------
__device__ __forceinline__ int block_exscan(int v, int* s_warp)
{
    __syncthreads();
    int lane = threadIdx.x & 31, warp = threadIdx.x >> 5;
    int incl = v;
#pragma unroll
    for (int o = 1; o < 32; o <<= 1) {
        int t = __shfl_up_sync(0xFFFFFFFFu, incl, o);
        if (lane >= o) incl += t;
    }
    if (lane == 31) s_warp[warp] = incl;
    __syncthreads();
    if (warp == 0 && lane < 16) {
        int w  = s_warp[lane];
        int wi = w;
#pragma unroll
        for (int o = 1; o < 16; o <<= 1) {
            int t = __shfl_up_sync(0x0000FFFFu, wi, o);
            if (lane >= o) wi += t;
        }
        s_warp[lane] = wi - w;
    }
    __syncthreads();
    return s_warp[warp] + incl - v;
}

__device__ __forceinline__ int block_exscan_tot(int v, int* s_warp, int* s_tot)
{
    __syncthreads();
    int lane = threadIdx.x & 31, warp = threadIdx.x >> 5;
    int incl = v;
#pragma unroll
    for (int o = 1; o < 32; o <<= 1) {
        int t = __shfl_up_sync(0xFFFFFFFFu, incl, o);
        if (lane >= o) incl += t;
    }
    if (lane == 31) s_warp[warp] = incl;
    __syncthreads();
    if (warp == 0 && lane < 16) {
        int w  = s_warp[lane];
        int wi = w;
#pragma unroll
        for (int o = 1; o < 16; o <<= 1) {
            int t = __shfl_up_sync(0x0000FFFFu, wi, o);
            if (lane >= o) wi += t;
        }
        if (lane == 15) *s_tot = wi;
        s_warp[lane] = wi - w;
    }
    __syncthreads();
    return s_warp[warp] + incl - v;
}

// ---------------------------------------------------------------------------
// Fused persistent kernel
// ---------------------------------------------------------------------------
__global__ __launch_bounds__(NT, 1) void topk_pool_kernel(
    const float* __restrict__ X, const float* __restrict__ A,
    const float* __restrict__ kern, float* __restrict__ out)
{
    __shared__ int h[2048];
    __shared__ int s_warp[16];
    __shared__ int s_tot;
    __shared__ float s_red[16];
    __shared__ unsigned s_B;
    __shared__ int s_after;
    __shared__ unsigned s_e0;

    int tid  = threadIdx.x;
    int lane = tid & 31, warp = tid >> 5;
    int bid  = blockIdx.x;

    if (tid == 0) s_e0 = *(volatile unsigned*)&g_bar_epoch;
    __syncthreads();
    unsigned e0 = s_e0;

    // ---------------- Phase 1: y = X @ kernel (warp handles 2 rows) ---------
    {
        const float4* k4 = (const float4*)kern;
        float4 kc[4];
#pragma unroll
        for (int it = 0; it < 4; it++) kc[it] = __ldg(&k4[lane + 32 * it]);

        int gw = bid * 16 + warp;                 // 2368 warps, 2 rows each iter
        for (int r = gw * 2; r < N_ROWS; r += NBLK * 16 * 2) {
            const float4* xa = (const float4*)(X + (size_t)r * F_DIM);
            const float4* xb = (const float4*)(X + (size_t)(r + 1) * F_DIM);
            float4 va[4], vb[4];
#pragma unroll
            for (int it = 0; it < 4; it++) { va[it] = xa[lane + 32 * it]; }
#pragma unroll
            for (int it = 0; it < 4; it++) { vb[it] = xb[lane + 32 * it]; }
            float aa = 0.f, ab = 0.f;
#pragma unroll
            for (int it = 0; it < 4; it++) {
                aa = fmaf(va[it].x, kc[it].x, aa);
                aa = fmaf(va[it].y, kc[it].y, aa);
                aa = fmaf(va[it].z, kc[it].z, aa);
                aa = fmaf(va[it].w, kc[it].w, aa);
                ab = fmaf(vb[it].x, kc[it].x, ab);
                ab = fmaf(vb[it].y, kc[it].y, ab);
                ab = fmaf(vb[it].z, kc[it].z, ab);
                ab = fmaf(vb[it].w, kc[it].w, ab);
            }
#pragma unroll
            for (int o = 16; o > 0; o >>= 1) {
                aa += __shfl_xor_sync(0xFFFFFFFFu, aa, o);
                ab += __shfl_xor_sync(0xFFFFFFFFu, ab, o);
            }
            if (lane == 0) { g_y[r] = aa; g_y[r + 1] = ab; }
        }
    }

    grid_barrier(1, e0);

    // ---------------- Phase 2: block 0 — radix select -----------------------
    if (bid == 0) {
        // inv_norm (F_DIM == NT == 512)
        float kv = kern[tid];
        float s = kv * kv;
#pragma unroll
        for (int o = 16; o > 0; o >>= 1) s += __shfl_xor_sync(0xFFFFFFFFu, s, o);
        if (lane == 0) s_red[warp] = s;
        __syncthreads();
        if (warp == 0 && lane < 16) {
            float t = s_red[lane];
#pragma unroll
            for (int o = 8; o > 0; o >>= 1) t += __shfl_xor_sync(0x0000FFFFu, t, o);
            if (lane == 0) { s_red[0] = rsqrtf(t); }
        }
        __syncthreads();
        if (tid == 0) g_inv_norm = s_red[0];

        // load 16 keys per thread (contiguous: tid*16 .. tid*16+15)
        const float4* y4 = (const float4*)g_y;
        unsigned key[16];
#pragma unroll
        for (int q = 0; q < 4; q++) {
            float4 a = y4[tid * 4 + q];
            float vv[4] = {a.x, a.y, a.z, a.w};
#pragma unroll
            for (int j = 0; j < 4; j++) {
                unsigned u = __float_as_uint(vv[j]);
                key[q * 4 + j] = (u & 0x80000000u) ? ~u : (u | 0x80000000u);
            }
        }

        const int shifts[3] = {21, 10, 0};
        const int nbv[3]    = {2048, 2048, 1024};
        unsigned prefix = 0, maskdone = 0;
        int krem = K_KEEP;

#pragma unroll 1
        for (int p = 0; p < 3; p++) {
            int nb = nbv[p];
            int shift = shifts[p];
            unsigned bmask = (unsigned)(nb - 1);
#pragma unroll
            for (int q = 0; q < 4; q++) h[tid + q * 512] = 0;
            __syncthreads();
#pragma unroll
            for (int j = 0; j < 16; j++)
                if ((key[j] & maskdone) == prefix)
                    atomicAdd(&h[(key[j] >> shift) & bmask], 1);
            __syncthreads();

            if (nb == 2048) {
                int v0 = h[4 * tid], v1 = h[4 * tid + 1], v2 = h[4 * tid + 2], v3 = h[4 * tid + 3];
                int tsum = v0 + v1 + v2 + v3;
                int ex = block_exscan_tot(tsum, s_warp, &s_tot);
                int total = s_tot;
                int suf0 = total - ex;
                int suf1 = suf0 - v0;
                int suf2 = suf1 - v1;
                int suf3 = suf2 - v2;
                int suf4 = suf3 - v3;
                if (suf0 >= krem && suf1 < krem) { s_B = 4u*tid + 0; s_after = suf1; }
                if (suf1 >= krem && suf2 < krem) { s_B = 4u*tid + 1; s_after = suf2; }
                if (suf2 >= krem && suf3 < krem) { s_B = 4u*tid + 2; s_after = suf3; }
                if (suf3 >= krem && suf4 < krem) { s_B = 4u*tid + 3; s_after = suf4; }
            } else {
                int v0 = h[2 * tid], v1 = h[2 * tid + 1];
                int tsum = v0 + v1;
                int ex = block_exscan_tot(tsum, s_warp, &s_tot);
                int total = s_tot;
                int suf0 = total - ex;
                int suf1 = suf0 - v0;
                int suf2 = suf1 - v1;
                if (suf0 >= krem && suf1 < krem) { s_B = 2u*tid + 0; s_after = suf1; }
                if (suf1 >= krem && suf2 < krem) { s_B = 2u*tid + 1; s_after = suf2; }
            }
            __syncthreads();
            prefix   |= s_B << shift;
            maskdone |= bmask << shift;
            krem     -= s_after;
            __syncthreads();
        }

        unsigned T = prefix;
        int tie_keep = krem;

        int myeq = 0;
#pragma unroll
        for (int j = 0; j < 16; j++) myeq += (key[j] == T);
        int eq_before = block_exscan(myeq, s_warp);

        bool keep[16];
        int e = eq_before, mykeep = 0;
#pragma unroll
        for (int j = 0; j < 16; j++) {
            if (key[j] == T) { keep[j] = (e < tie_keep); e++; }
            else             { keep[j] = (key[j] > T); }
            mykeep += keep[j];
        }
        int pos = block_exscan(mykeep, s_warp);
#pragma unroll
        for (int j = 0; j < 16; j++)
            if (keep[j]) g_idx[pos++] = tid * 16 + j;
    }

    grid_barrier(2, e0);

    // ---------------- Phase 3: gathers --------------------------------------
    // X_pooled: 4 rows per block-iteration (128 threads per row)
    {
        float inv_norm = g_inv_norm;
        for (int g = bid; g < K_KEEP / 4; g += NBLK) {
            int r   = g * 4 + (tid >> 7);
            int t   = tid & 127;
            int row = g_idx[r];
            float gate = tanhf(g_y[row] * inv_norm);
            const float4* xr = (const float4*)(X + (size_t)row * F_DIM);
            float4* o = (float4*)(out + (size_t)r * F_DIM);
            float4 x = xr[t];
            o[t] = make_float4(x.x * gate, x.y * gate, x.z * gate, x.w * gate);
        }
    }
    // A_pooled: one row per block-iteration (1024 float4 = 512 threads x 2)
    {
        const int4* idx4 = (const int4*)g_idx;
        float* outA = out + (size_t)K_KEEP * F_DIM;
        for (int r = bid; r < K_KEEP; r += NBLK) {
            const float* rowp = A + (size_t)g_idx[r] * N_ROWS;
            float4* o = (float4*)(outA + (size_t)r * K_KEEP);
#pragma unroll
            for (int it = 0; it < 2; it++) {
                int c = tid + it * 512;
                int4 i = __ldg(&idx4[c]);
                float4 v;
                v.x = __ldcs(&rowp[i.x]);
                v.y = __ldcs(&rowp[i.y]);
                v.z = __ldcs(&rowp[i.z]);
                v.w = __ldcs(&rowp[i.w]);
                __stcs(&o[c], v);
            }
        }
    }
}

// ---------------------------------------------------------------------------
extern "C" void kernel_launch(void* const* d_in, const int* in_sizes, int n_in,
                              void* d_out, int out_size)
{
    const float* X    = (const float*)d_in[0];
    const float* A    = (const float*)d_in[1];
    const float* kern = (const float*)d_in[2];
    float* out = (float*)d_out;

    topk_pool_kernel<<<NBLK, NT>>>(X, A, kern, out);
}

// round 6
// speedup vs baseline: 1.3901x; 1.3901x over previous
#include <cuda_runtime.h>
#include <cuda_bf16.h>

#define N_ROWS 8192
#define F_DIM  512
#define K_KEEP 4096
#define NBLK   148
#define NT     512

// Scratch (device globals — no allocation allowed)
__device__ __align__(16) float g_y[N_ROWS];
__device__ float g_inv_norm;
__device__ __align__(16) int   g_idx[K_KEEP];
__device__ unsigned g_count = 0;    // arrive counter; reset by block 0 each launch

// ---------------------------------------------------------------------------
// Block scans for 512 threads (16 warps)
// ---------------------------------------------------------------------------
__device__ __forceinline__ int block_exscan(int v, int* s_warp)
{
    __syncthreads();
    int lane = threadIdx.x & 31, warp = threadIdx.x >> 5;
    int incl = v;
#pragma unroll
    for (int o = 1; o < 32; o <<= 1) {
        int t = __shfl_up_sync(0xFFFFFFFFu, incl, o);
        if (lane >= o) incl += t;
    }
    if (lane == 31) s_warp[warp] = incl;
    __syncthreads();
    if (warp == 0 && lane < 16) {
        int w  = s_warp[lane];
        int wi = w;
#pragma unroll
        for (int o = 1; o < 16; o <<= 1) {
            int t = __shfl_up_sync(0x0000FFFFu, wi, o);
            if (lane >= o) wi += t;
        }
        s_warp[lane] = wi - w;
    }
    __syncthreads();
    return s_warp[warp] + incl - v;
}

__device__ __forceinline__ int block_exscan_tot(int v, int* s_warp, int* s_tot)
{
    __syncthreads();
    int lane = threadIdx.x & 31, warp = threadIdx.x >> 5;
    int incl = v;
#pragma unroll
    for (int o = 1; o < 32; o <<= 1) {
        int t = __shfl_up_sync(0xFFFFFFFFu, incl, o);
        if (lane >= o) incl += t;
    }
    if (lane == 31) s_warp[warp] = incl;
    __syncthreads();
    if (warp == 0 && lane < 16) {
        int w  = s_warp[lane];
        int wi = w;
#pragma unroll
        for (int o = 1; o < 16; o <<= 1) {
            int t = __shfl_up_sync(0x0000FFFFu, wi, o);
            if (lane >= o) wi += t;
        }
        if (lane == 15) *s_tot = wi;
        s_warp[lane] = wi - w;
    }
    __syncthreads();
    return s_warp[warp] + incl - v;
}

// ---------------------------------------------------------------------------
// Kernel 1: y = X @ kernel on all blocks; non-zero blocks arrive & exit;
// block 0 waits for all arrivals then runs the 3-pass radix select.
// ---------------------------------------------------------------------------
__global__ __launch_bounds__(NT, 1) void score_select_kernel(
    const float* __restrict__ X, const float* __restrict__ kern)
{
    __shared__ int h[2048];
    __shared__ int s_warp[16];
    __shared__ int s_tot;
    __shared__ float s_red[16];
    __shared__ unsigned s_B;
    __shared__ int s_after;

    int tid  = threadIdx.x;
    int lane = tid & 31, warp = tid >> 5;
    int bid  = blockIdx.x;

    // ---------------- Phase 1: scores (warp handles 2 rows per iter) --------
    {
        const float4* k4 = (const float4*)kern;
        float4 kc[4];
#pragma unroll
        for (int it = 0; it < 4; it++) kc[it] = __ldg(&k4[lane + 32 * it]);

        int gw = bid * 16 + warp;                 // 2368 warps
        for (int r = gw * 2; r < N_ROWS; r += NBLK * 16 * 2) {
            const float4* xa = (const float4*)(X + (size_t)r * F_DIM);
            const float4* xb = (const float4*)(X + (size_t)(r + 1) * F_DIM);
            float4 va[4], vb[4];
#pragma unroll
            for (int it = 0; it < 4; it++) va[it] = xa[lane + 32 * it];
#pragma unroll
            for (int it = 0; it < 4; it++) vb[it] = xb[lane + 32 * it];
            float aa = 0.f, ab = 0.f;
#pragma unroll
            for (int it = 0; it < 4; it++) {
                aa = fmaf(va[it].x, kc[it].x, aa);
                aa = fmaf(va[it].y, kc[it].y, aa);
                aa = fmaf(va[it].z, kc[it].z, aa);
                aa = fmaf(va[it].w, kc[it].w, aa);
                ab = fmaf(vb[it].x, kc[it].x, ab);
                ab = fmaf(vb[it].y, kc[it].y, ab);
                ab = fmaf(vb[it].z, kc[it].z, ab);
                ab = fmaf(vb[it].w, kc[it].w, ab);
            }
#pragma unroll
            for (int o = 16; o > 0; o >>= 1) {
                aa += __shfl_xor_sync(0xFFFFFFFFu, aa, o);
                ab += __shfl_xor_sync(0xFFFFFFFFu, ab, o);
            }
            if (lane == 0) { g_y[r] = aa; g_y[r + 1] = ab; }
        }
    }

    __syncthreads();
    if (bid != 0) {
        if (tid == 0) { __threadfence(); atomicAdd(&g_count, 1); }
        return;                                   // non-zero blocks done
    }

    // ---------------- Block 0: wait for all other blocks --------------------
    if (tid == 0) {
        int backoff = 32;
        while (*(volatile unsigned*)&g_count < NBLK - 1) {
            __nanosleep(backoff);
            if (backoff < 256) backoff <<= 1;
        }
        g_count = 0;                              // reset for next launch
        __threadfence();
    }
    __syncthreads();

    // ---------------- Phase 2: radix select ---------------------------------
    // inv_norm (F_DIM == NT == 512)
    {
        float kv = kern[tid];
        float s = kv * kv;
#pragma unroll
        for (int o = 16; o > 0; o >>= 1) s += __shfl_xor_sync(0xFFFFFFFFu, s, o);
        if (lane == 0) s_red[warp] = s;
        __syncthreads();
        if (warp == 0 && lane < 16) {
            float t = s_red[lane];
#pragma unroll
            for (int o = 8; o > 0; o >>= 1) t += __shfl_xor_sync(0x0000FFFFu, t, o);
            if (lane == 0) s_red[0] = rsqrtf(t);
        }
        __syncthreads();
        if (tid == 0) g_inv_norm = s_red[0];
    }

    // load 16 keys per thread (contiguous: tid*16 .. tid*16+15)
    const float4* y4 = (const float4*)g_y;
    unsigned key[16];
#pragma unroll
    for (int q = 0; q < 4; q++) {
        float4 a = y4[tid * 4 + q];
        float vv[4] = {a.x, a.y, a.z, a.w};
#pragma unroll
        for (int j = 0; j < 4; j++) {
            unsigned u = __float_as_uint(vv[j]);
            key[q * 4 + j] = (u & 0x80000000u) ? ~u : (u | 0x80000000u);
        }
    }

    const int shifts[3] = {21, 10, 0};
    const int nbv[3]    = {2048, 2048, 1024};
    unsigned prefix = 0, maskdone = 0;
    int krem = K_KEEP;

#pragma unroll 1
    for (int p = 0; p < 3; p++) {
        int nb = nbv[p];
        int shift = shifts[p];
        unsigned bmask = (unsigned)(nb - 1);
#pragma unroll
        for (int q = 0; q < 4; q++) h[tid + q * 512] = 0;
        __syncthreads();
#pragma unroll
        for (int j = 0; j < 16; j++)
            if ((key[j] & maskdone) == prefix)
                atomicAdd(&h[(key[j] >> shift) & bmask], 1);
        __syncthreads();

        if (nb == 2048) {
            int v0 = h[4 * tid], v1 = h[4 * tid + 1], v2 = h[4 * tid + 2], v3 = h[4 * tid + 3];
            int tsum = v0 + v1 + v2 + v3;
            int ex = block_exscan_tot(tsum, s_warp, &s_tot);
            int total = s_tot;
            int suf0 = total - ex;
            int suf1 = suf0 - v0;
            int suf2 = suf1 - v1;
            int suf3 = suf2 - v2;
            int suf4 = suf3 - v3;
            if (suf0 >= krem && suf1 < krem) { s_B = 4u*tid + 0; s_after = suf1; }
            if (suf1 >= krem && suf2 < krem) { s_B = 4u*tid + 1; s_after = suf2; }
            if (suf2 >= krem && suf3 < krem) { s_B = 4u*tid + 2; s_after = suf3; }
            if (suf3 >= krem && suf4 < krem) { s_B = 4u*tid + 3; s_after = suf4; }
        } else {
            int v0 = h[2 * tid], v1 = h[2 * tid + 1];
            int tsum = v0 + v1;
            int ex = block_exscan_tot(tsum, s_warp, &s_tot);
            int total = s_tot;
            int suf0 = total - ex;
            int suf1 = suf0 - v0;
            int suf2 = suf1 - v1;
            if (suf0 >= krem && suf1 < krem) { s_B = 2u*tid + 0; s_after = suf1; }
            if (suf1 >= krem && suf2 < krem) { s_B = 2u*tid + 1; s_after = suf2; }
        }
        __syncthreads();
        prefix   |= s_B << shift;
        maskdone |= bmask << shift;
        krem     -= s_after;
        __syncthreads();
    }

    unsigned T = prefix;
    int tie_keep = krem;

    int myeq = 0;
#pragma unroll
    for (int j = 0; j < 16; j++) myeq += (key[j] == T);
    int eq_before = block_exscan(myeq, s_warp);

    bool keep[16];
    int e = eq_before, mykeep = 0;
#pragma unroll
    for (int j = 0; j < 16; j++) {
        if (key[j] == T) { keep[j] = (e < tie_keep); e++; }
        else             { keep[j] = (key[j] > T); }
        mykeep += keep[j];
    }
    int pos = block_exscan(mykeep, s_warp);
#pragma unroll
    for (int j = 0; j < 16; j++)
        if (keep[j]) g_idx[pos++] = tid * 16 + j;
}

// ---------------------------------------------------------------------------
// Kernel 2: fused gather. A-blocks first (long pole), X-blocks after.
//   blocks [0, 4096):      A_pooled — one A-row gather per block
//   blocks [4096, 6144):   X_pooled — 2 rows per block, tanh gating
// ---------------------------------------------------------------------------
__global__ __launch_bounds__(256) void gather_kernel(
    const float* __restrict__ X, const float* __restrict__ A,
    float* __restrict__ out)
{
    int bid = blockIdx.x;
    int tid = threadIdx.x;
    if (bid < K_KEEP) {
        int r = bid;
        const float* rowp = A + (size_t)g_idx[r] * N_ROWS;
        const int4* idx4 = (const int4*)g_idx;
        float4* o = (float4*)(out + (size_t)K_KEEP * F_DIM + (size_t)r * K_KEEP);
#pragma unroll
        for (int it = 0; it < 4; it++) {
            int c = tid + it * 256;
            int4 i = __ldg(&idx4[c]);
            float4 v;
            v.x = __ldcs(&rowp[i.x]);
            v.y = __ldcs(&rowp[i.y]);
            v.z = __ldcs(&rowp[i.z]);
            v.w = __ldcs(&rowp[i.w]);
            __stcs(&o[c], v);
        }
    } else {
        int r   = (bid - K_KEEP) * 2 + (tid >> 7);
        int t   = tid & 127;
        int row = g_idx[r];
        float gate = tanhf(g_y[row] * g_inv_norm);
        const float4* xr = (const float4*)(X + (size_t)row * F_DIM);
        float4* o = (float4*)(out + (size_t)r * F_DIM);
        float4 x = xr[t];
        o[t] = make_float4(x.x * gate, x.y * gate, x.z * gate, x.w * gate);
    }
}

// ---------------------------------------------------------------------------
extern "C" void kernel_launch(void* const* d_in, const int* in_sizes, int n_in,
                              void* d_out, int out_size)
{
    const float* X    = (const float*)d_in[0];
    const float* A    = (const float*)d_in[1];
    const float* kern = (const float*)d_in[2];
    float* out = (float*)d_out;

    score_select_kernel<<<NBLK, NT>>>(X, kern);
    gather_kernel<<<K_KEEP + 2048, 256>>>(X, A, out);
}